// round 6
// baseline (speedup 1.0000x reference)
#include <cuda_runtime.h>

#define DD 64
#define FF 8
#define ZZ 72          // D + F
#define HH 256
#define TT 50
#define TUU 128
#define CTAS 128
#define NT 512

typedef unsigned long long u64;

__device__ __forceinline__ u64 fma2(u64 a, u64 b, u64 c) {
    u64 d;
    asm("fma.rn.f32x2 %0, %1, %2, %3;" : "=l"(d) : "l"(a), "l"(b), "l"(c));
    return d;
}
__device__ __forceinline__ u64 pack2(float lo, float hi) {
    u64 d;
    asm("mov.b64 %0, {%1, %2};" : "=l"(d) : "f"(lo), "f"(hi));
    return d;
}
__device__ __forceinline__ float2 unpack2(u64 v) {
    float lo, hi;
    asm("mov.b64 {%0, %1}, %2;" : "=f"(lo), "=f"(hi) : "l"(v));
    return make_float2(lo, hi);
}
// tanh(x) = 1 - 2/(exp(2x)+1) via ex2.approx + rcp.approx, abs err ~1e-6.
__device__ __forceinline__ float fast_tanh(float x) {
    float e, r;
    asm("ex2.approx.f32 %0, %1;" : "=f"(e) : "f"(x * 2.8853900817779268f));
    asm("rcp.approx.f32 %0, %1;" : "=f"(r) : "f"(e + 1.0f));
    return fmaf(-2.0f, r, 1.0f);
}

// Named barriers: 1+G z-ready[G] (cnt 512), 5+G h-ready[G] (cnt 512),
//                 9 L1-internal (256), 10 L2-internal (256)
#define BSYNC(id, cnt) asm volatile("bar.sync %0, %1;"   :: "r"(id), "n"(cnt) : "memory")
#define BARV(id, cnt)  asm volatile("bar.arrive %0, %1;" :: "r"(id), "n"(cnt) : "memory")

// SMEM floats: ubuf 8192 | zbuf 4*144=576 | hbuf 4*512=2048 |
//              p1 512 | p2 2*1024=2048 | te 64 | tu 128
#define SMEM_FLOATS (8192 + 576 + 2048 + 512 + 2048 + 64 + 128)

// exact jnp.searchsorted(side='right')-1 semantics
__device__ __forceinline__ void u_interp(float* zG, const float* tu,
                                         const float* ub, int G, int o,
                                         float tst) {
    int r = o >> 3, f = o & 7;
    int idx = (int)floorf(tst * (float)(TUU - 1));
    idx = max(0, min(TUU - 2, idx));
    while (idx > 0 && tu[idx] > tst) --idx;
    while (idx < TUU - 2 && tu[idx + 1] <= tst) ++idx;
    float t0 = tu[idx], t1 = tu[idx + 1];
    float w = (tst - t0) / (t1 - t0);
    const float* ur = ub + (G * 2 + r) * (TUU * FF);
    float u0 = ur[idx * FF + f], u1 = ur[(idx + 1) * FF + f];
    zG[r * ZZ + DD + f] = u0 + w * (u1 - u0);
}

__global__ void __launch_bounds__(NT, 1)
node_kernel(const float* __restrict__ x0g, const float* __restrict__ te_g,
            const float* __restrict__ tu_g, const float* __restrict__ u_g,
            const float* __restrict__ W1g, const float* __restrict__ b1g,
            const float* __restrict__ W2g, const float* __restrict__ b2g,
            float* __restrict__ out)
{
    extern __shared__ float sm[];
    float* ubuf = sm;                  // [8][TUU][FF]
    float* zbuf = ubuf + 8192;         // [4][2][ZZ]
    float* hbuf = zbuf + 576;          // [4][2][HH]
    float* p1f  = hbuf + 2048;         // [2][128] u64
    float* p2f  = p1f + 512;           // 2 bufs x [2][8][32] u64
    float* te   = p2f + 2048;          // [64]
    float* tu   = te + 64;             // [TUU]
    u64* hq  = reinterpret_cast<u64*>(hbuf);
    u64* p1q = reinterpret_cast<u64*>(p1f);
    u64* p2q = reinterpret_cast<u64*>(p2f);

    const int tid = threadIdx.x;
    const int b0  = blockIdx.x * 8;

    // ---- one-time smem loads ----
    for (int i = tid; i < TT;  i += NT) te[i] = te_g[i];
    for (int i = tid; i < TUU; i += NT) tu[i] = tu_g[i];
    for (int i = tid; i < 8 * TUU * FF; i += NT) {
        int r = i / (TUU * FF);
        int o = i - r * (TUU * FF);
        ubuf[i] = u_g[(size_t)(b0 + r) * (TUU * FF) + o];
    }

    if (tid < 256) {
        // ================= LAYER-1 WORKERS (warps 0-7) =================
        // thread (half, t): cols j0=2t, j0+1; K-half [half*36, +36)
        const int half = tid >> 7;
        const int t    = tid & 127;
        const int j0   = 2 * t;
        u64 w1a[18], w1b[18];
#pragma unroll
        for (int i = 0; i < 18; ++i) {
            int k = half * 36 + 2 * i;
            w1a[i] = pack2(W1g[k * HH + j0],     W1g[(k + 1) * HH + j0]);
            w1b[i] = pack2(W1g[k * HH + j0 + 1], W1g[(k + 1) * HH + j0 + 1]);
        }
        const float b10 = b1g[j0], b11 = b1g[j0 + 1];
        const int mr = half;       // row I combine
        const int dr = 1 - half;   // row I donate

        __syncthreads();

        for (int it = 0; it < 196 * 6; ++it) {
#pragma unroll
            for (int G = 0; G < 4; ++G) {
                BSYNC(1 + G, 512);                 // z(G) ready
                const float* zb = zbuf + G * 144 + half * 36;
                float pr0[2], pr1[2];
#pragma unroll
                for (int r = 0; r < 2; ++r) {
                    const ulonglong2* zr =
                        reinterpret_cast<const ulonglong2*>(zb + r * ZZ);
                    u64 a0 = 0ull, a1 = 0ull, c0 = 0ull, c1 = 0ull;
#pragma unroll
                    for (int i = 0; i < 9; ++i) {  // 9 LDS.128, 36 FMA2
                        ulonglong2 zz = zr[i];
                        a0 = fma2(zz.x, w1a[2 * i],     a0);
                        a1 = fma2(zz.y, w1a[2 * i + 1], a1);
                        c0 = fma2(zz.x, w1b[2 * i],     c0);
                        c1 = fma2(zz.y, w1b[2 * i + 1], c1);
                    }
                    float2 fa = unpack2(a0), fb = unpack2(a1);
                    float2 fc = unpack2(c0), fd = unpack2(c1);
                    pr0[r] = (fa.x + fa.y) + (fb.x + fb.y);
                    pr1[r] = (fc.x + fc.y) + (fd.x + fd.y);
                }
                p1q[dr * 128 + t] = pack2(pr0[dr], pr1[dr]);
                BSYNC(9, 256);                     // L1-internal
                float2 pp = unpack2(p1q[mr * 128 + t]);
                hq[G * 256 + mr * 128 + t] =
                    pack2(fast_tanh(pr0[mr] + pp.x + b10),
                          fast_tanh(pr1[mr] + pp.y + b11));
                BARV(5 + G, 512);                  // h(G) ready
            }
        }
    } else {
        // ================= LAYER-2 WORKERS (warps 8-15) =================
        // thread (pg, dp): cols 2dp, 2dp+1; K-slice [pg*32, +32).
        // Owner: group myG=i2>>6, row myr=(i2>>5)&1, col-pair mycp=i2&31.
        const int i2 = tid - 256;
        const int pg = i2 >> 5;
        const int dp = i2 & 31;
        const int c0 = 2 * dp;
        const int myG  = i2 >> 6;
        const int myr  = (i2 >> 5) & 1;
        const int mycp = i2 & 31;
        const int o63  = i2 & 63;
        u64 w2a[16], w2b[16];
#pragma unroll
        for (int i = 0; i < 16; ++i) {
            int k = pg * 32 + 2 * i;
            w2a[i] = pack2(W2g[k * DD + c0],     W2g[(k + 1) * DD + c0]);
            w2b[i] = pack2(W2g[k * DD + c0 + 1], W2g[(k + 1) * DD + c0 + 1]);
        }
        const float b20 = b2g[2 * mycp], b21 = b2g[2 * mycp + 1];

        const size_t grow = (size_t)(b0 + 2 * myG + myr);
        float xc0 = x0g[grow * DD + 2 * mycp];
        float xc1 = x0g[grow * DD + 2 * mycp + 1];
        out[grow * (TT * DD) + 2 * mycp]     = xc0;   // t index 0
        out[grow * (TT * DD) + 2 * mycp + 1] = xc1;
        float kk0[6], kk1[6];

        __syncthreads();

        // prologue: z stage-0 for all 4 groups
#pragma unroll
        for (int G = 0; G < 4; ++G) {
            if (myG == G) {
                float* zG = zbuf + G * 144;
                zG[myr * ZZ + 2 * mycp]     = xc0;
                zG[myr * ZZ + 2 * mycp + 1] = xc1;
                if (o63 < 16) u_interp(zG, tu, ubuf, G, o63, te[0]);
            }
            BARV(1 + G, 512);
        }

        for (int m = 0; m < 196; ++m) {
            const int ci = m >> 2, s = m & 3;
            const float tc0 = te[ci];
            const float dtc = te[ci + 1] - tc0;
            const float dt  = dtc * 0.25f;
            const float tsub = tc0 + dtc * ((float)s * 0.25f);
            for (int st = 0; st < 6; ++st) {
#pragma unroll
                for (int G = 0; G < 4; ++G) {
                    BSYNC(5 + G, 512);             // h(G) ready
                    const float* hb = hbuf + G * 512 + pg * 32;
                    u64* p2b = p2q + (G & 1) * 512;
#pragma unroll
                    for (int r = 0; r < 2; ++r) {
                        const ulonglong2* hr =
                            reinterpret_cast<const ulonglong2*>(hb + r * HH);
                        u64 a0 = 0ull, a1 = 0ull, d0 = 0ull, d1 = 0ull;
#pragma unroll
                        for (int i = 0; i < 8; ++i) {  // 8 LDS.128, 32 FMA2
                            ulonglong2 hh = hr[i];
                            a0 = fma2(hh.x, w2a[2 * i],     a0);
                            a1 = fma2(hh.y, w2a[2 * i + 1], a1);
                            d0 = fma2(hh.x, w2b[2 * i],     d0);
                            d1 = fma2(hh.y, w2b[2 * i + 1], d1);
                        }
                        float2 fa = unpack2(a0), fb = unpack2(a1);
                        float2 fc = unpack2(d0), fd = unpack2(d1);
                        p2b[r * 256 + pg * 32 + dp] =
                            pack2((fa.x + fa.y) + (fb.x + fb.y),
                                  (fc.x + fc.y) + (fd.x + fd.y));
                    }
                    BSYNC(10, 256);                // L2-internal
                    const bool last = (m == 195) && (st == 5);
                    if (myG == G) {
                        const u64* pe = p2b + myr * 256 + mycp;
                        float kv0 = b20, kv1 = b21;
#pragma unroll
                        for (int pgi = 0; pgi < 8; ++pgi) {
                            float2 v = unpack2(pe[pgi * 32]);
                            kv0 += v.x; kv1 += v.y;
                        }
                        kk0[st] = kv0; kk1[st] = kv1;
                        float* zG = zbuf + G * 144;
                        if (st < 5) {
                            float xs0, xs1;
                            switch (st) {
                            case 0:
                                xs0 = xc0 + dt * (0.2f * kk0[0]);
                                xs1 = xc1 + dt * (0.2f * kk1[0]); break;
                            case 1:
                                xs0 = xc0 + dt * (0.075f * kk0[0] + 0.225f * kk0[1]);
                                xs1 = xc1 + dt * (0.075f * kk1[0] + 0.225f * kk1[1]); break;
                            case 2:
                                xs0 = xc0 + dt * ((float)(44.0/45.0) * kk0[0]
                                    + (float)(-56.0/15.0) * kk0[1]
                                    + (float)(32.0/9.0) * kk0[2]);
                                xs1 = xc1 + dt * ((float)(44.0/45.0) * kk1[0]
                                    + (float)(-56.0/15.0) * kk1[1]
                                    + (float)(32.0/9.0) * kk1[2]); break;
                            case 3:
                                xs0 = xc0 + dt * ((float)(19372.0/6561.0) * kk0[0]
                                    + (float)(-25360.0/2187.0) * kk0[1]
                                    + (float)(64448.0/6561.0) * kk0[2]
                                    + (float)(-212.0/729.0) * kk0[3]);
                                xs1 = xc1 + dt * ((float)(19372.0/6561.0) * kk1[0]
                                    + (float)(-25360.0/2187.0) * kk1[1]
                                    + (float)(64448.0/6561.0) * kk1[2]
                                    + (float)(-212.0/729.0) * kk1[3]); break;
                            default:
                                xs0 = xc0 + dt * ((float)(9017.0/3168.0) * kk0[0]
                                    + (float)(-355.0/33.0) * kk0[1]
                                    + (float)(46732.0/5247.0) * kk0[2]
                                    + (float)(49.0/176.0) * kk0[3]
                                    + (float)(-5103.0/18656.0) * kk0[4]);
                                xs1 = xc1 + dt * ((float)(9017.0/3168.0) * kk1[0]
                                    + (float)(-355.0/33.0) * kk1[1]
                                    + (float)(46732.0/5247.0) * kk1[2]
                                    + (float)(49.0/176.0) * kk1[3]
                                    + (float)(-5103.0/18656.0) * kk1[4]); break;
                            }
                            zG[myr * ZZ + 2 * mycp]     = xs0;
                            zG[myr * ZZ + 2 * mycp + 1] = xs1;
                            if (o63 < 16) {
                                const float CSTN[5] = {0.2f, 0.3f, 0.8f,
                                                       (float)(8.0/9.0), 1.0f};
                                u_interp(zG, tu, ubuf, G, o63,
                                         tsub + CSTN[st] * dt);
                            }
                        } else {
                            const float B1 = (float)(35.0/384.0),
                                        B3 = (float)(500.0/1113.0),
                                        B4 = (float)(125.0/192.0),
                                        B5 = (float)(-2187.0/6784.0),
                                        B6 = (float)(11.0/84.0);
                            float xn0 = xc0 + dt * (B1 * kk0[0] + B3 * kk0[2]
                                      + B4 * kk0[3] + B5 * kk0[4] + B6 * kv0);
                            float xn1 = xc1 + dt * (B1 * kk1[0] + B3 * kk1[2]
                                      + B4 * kk1[3] + B5 * kk1[4] + B6 * kv1);
                            xc0 = xn0; xc1 = xn1;
                            if (s == 3) {
                                out[grow * (TT * DD) + (ci + 1) * DD + 2 * mycp]     = xn0;
                                out[grow * (TT * DD) + (ci + 1) * DD + 2 * mycp + 1] = xn1;
                            }
                            if (m < 195) {
                                zG[myr * ZZ + 2 * mycp]     = xn0;
                                zG[myr * ZZ + 2 * mycp + 1] = xn1;
                                float tn = (s < 3)
                                    ? tc0 + dtc * ((float)(s + 1) * 0.25f)
                                    : te[ci + 1];
                                if (o63 < 16) u_interp(zG, tu, ubuf, G, o63, tn);
                            }
                        }
                    }
                    if (!last) BARV(1 + G, 512);   // z(G) ready
                }
            }
        }
    }
}

extern "C" void kernel_launch(void* const* d_in, const int* in_sizes, int n_in,
                              void* d_out, int out_size) {
    const float* x0 = (const float*)d_in[0];
    const float* te = (const float*)d_in[1];
    const float* tu = (const float*)d_in[2];
    const float* ub = (const float*)d_in[3];
    const float* W1 = (const float*)d_in[4];
    const float* b1 = (const float*)d_in[5];
    const float* W2 = (const float*)d_in[6];
    const float* b2 = (const float*)d_in[7];
    float* out = (float*)d_out;

    const int smem_bytes = SMEM_FLOATS * (int)sizeof(float);   // 54272 B
    cudaFuncSetAttribute(node_kernel,
                         cudaFuncAttributeMaxDynamicSharedMemorySize, smem_bytes);
    node_kernel<<<CTAS, NT, smem_bytes>>>(x0, te, tu, ub, W1, b1, W2, b2, out);
}

// round 8
// speedup vs baseline: 1.3627x; 1.3627x over previous
#include <cuda_runtime.h>

#define DD 64
#define FF 8
#define ZZ 72          // D + F
#define HH 256
#define TT 50
#define TUU 128
#define CTAS 128
#define NT 512

typedef unsigned long long u64;

__device__ __forceinline__ u64 fma2(u64 a, u64 b, u64 c) {
    u64 d;
    asm("fma.rn.f32x2 %0, %1, %2, %3;" : "=l"(d) : "l"(a), "l"(b), "l"(c));
    return d;
}
__device__ __forceinline__ u64 pack2(float lo, float hi) {
    u64 d;
    asm("mov.b64 %0, {%1, %2};" : "=l"(d) : "f"(lo), "f"(hi));
    return d;
}
__device__ __forceinline__ float2 unpack2(u64 v) {
    float lo, hi;
    asm("mov.b64 {%0, %1}, %2;" : "=f"(lo), "=f"(hi) : "l"(v));
    return make_float2(lo, hi);
}
// tanh(x) = 1 - 2/(exp(2x)+1) via ex2.approx + rcp.approx, abs err ~1e-6.
__device__ __forceinline__ float fast_tanh(float x) {
    float e, r;
    asm("ex2.approx.f32 %0, %1;" : "=f"(e) : "f"(x * 2.8853900817779268f));
    asm("rcp.approx.f32 %0, %1;" : "=f"(r) : "f"(e + 1.0f));
    return fmaf(-2.0f, r, 1.0f);
}

// Named barriers (id 0 reserved for __syncthreads):
//   1+G : zready[G]  (L2 arrives 256, L1 syncs 256; count 512)
//   3+G : hready[G]  (L1 arrives 256, L2 syncs 256; count 512)
//   6   : L2-internal partial barrier (count 256)
#define BSYNC(id, cnt) asm volatile("bar.sync %0, %1;"   :: "r"(id), "n"(cnt) : "memory")
#define BARV(id, cnt)  asm volatile("bar.arrive %0, %1;" :: "r"(id), "n"(cnt) : "memory")

// SMEM floats: ubuf 8192 | zbuf 2*4*72=576 | hbuf 2*4*256=2048 | p2 2048 | te 64 | tu 128
#define SMEM_FLOATS (8192 + 576 + 2048 + 2048 + 64 + 128)

// exact jnp.searchsorted(side='right')-1 semantics
__device__ __forceinline__ void u_interp(float* zG, const float* tu,
                                         const float* ub, int G, int i2,
                                         float tst) {
    int r = i2 >> 3, f = i2 & 7;
    int idx = (int)floorf(tst * (float)(TUU - 1));
    idx = max(0, min(TUU - 2, idx));
    while (idx > 0 && tu[idx] > tst) --idx;
    while (idx < TUU - 2 && tu[idx + 1] <= tst) ++idx;
    float t0 = tu[idx], t1 = tu[idx + 1];
    float w = (tst - t0) / (t1 - t0);
    const float* ur = ub + (G * 4 + r) * (TUU * FF);
    float u0 = ur[idx * FF + f], u1 = ur[(idx + 1) * FF + f];
    zG[r * ZZ + DD + f] = u0 + w * (u1 - u0);
}

__global__ void __launch_bounds__(NT, 1)
node_kernel(const float* __restrict__ x0g, const float* __restrict__ te_g,
            const float* __restrict__ tu_g, const float* __restrict__ u_g,
            const float* __restrict__ W1g, const float* __restrict__ b1g,
            const float* __restrict__ W2g, const float* __restrict__ b2g,
            float* __restrict__ out)
{
    extern __shared__ float sm[];
    float* ubuf = sm;                  // [8][TUU][FF]
    float* zbuf = ubuf + 8192;         // [2][4][ZZ]
    float* hbuf = zbuf + 576;          // [2][4][HH]
    float* p2   = hbuf + 2048;         // [4][8][64] layer-2 partials
    float* te   = p2 + 2048;           // [64]
    float* tu   = te + 64;             // [TUU]
    u64* hq  = reinterpret_cast<u64*>(hbuf);
    u64* p2q = reinterpret_cast<u64*>(p2);

    const int tid = threadIdx.x;
    const int b0  = blockIdx.x * 8;

    // ---- one-time smem loads ----
    for (int i = tid; i < TT;  i += NT) te[i] = te_g[i];
    for (int i = tid; i < TUU; i += NT) tu[i] = tu_g[i];
    for (int i = tid; i < 8 * TUU * FF; i += NT) {
        int r = i / (TUU * FF);
        int o = i - r * (TUU * FF);
        ubuf[i] = u_g[(size_t)(b0 + r) * (TUU * FF) + o];
    }

    // Dopri5 tableau (fp32-rounded)
    const float A21 = 0.2f;
    const float A31 = 0.075f,                    A32 = 0.225f;
    const float A41 = (float)( 44.0/45.0),       A42 = (float)(-56.0/15.0),
                A43 = (float)( 32.0/9.0);
    const float A51 = (float)( 19372.0/6561.0),  A52 = (float)(-25360.0/2187.0),
                A53 = (float)( 64448.0/6561.0),  A54 = (float)(-212.0/729.0);
    const float A61 = (float)( 9017.0/3168.0),   A62 = (float)(-355.0/33.0),
                A63 = (float)( 46732.0/5247.0),  A64 = (float)( 49.0/176.0),
                A65 = (float)(-5103.0/18656.0);
    const float B1  = (float)( 35.0/384.0),      B3  = (float)(500.0/1113.0),
                B4  = (float)(125.0/192.0),      B5  = (float)(-2187.0/6784.0),
                B6  = (float)( 11.0/84.0);

    if (tid < 256) {
        // ================= LAYER-1 WORKERS (warps 0-7) =================
        // Lane pair (2k, 2k+1) owns cols (j0, j0+1); half = tid&1 owns
        // K-range [half*36, +36). Combine via shfl_xor(1): each lane SENDS
        // the rows its partner finalizes (p[dr+q]) and by symmetry RECEIVES
        // the partner's partial for its own rows (p[fr+q]).
        const int t    = tid >> 1;     // col-pair index 0..127
        const int half = tid & 1;
        const int j0   = 2 * t;
        u64 w1a[18], w1b[18];
#pragma unroll
        for (int i = 0; i < 18; ++i) {
            int k = half * 36 + 2 * i;
            w1a[i] = pack2(W1g[k * HH + j0],     W1g[(k + 1) * HH + j0]);
            w1b[i] = pack2(W1g[k * HH + j0 + 1], W1g[(k + 1) * HH + j0 + 1]);
        }
        const float b10 = b1g[j0], b11 = b1g[j0 + 1];
        const int fr = half * 2;       // rows I finalize: {0,1} or {2,3}
        const int dr = 2 - fr;         // rows I donate (partner finalizes)

        __syncthreads();               // init complete

        for (int it = 0; it < 196 * 6; ++it) {
#pragma unroll
            for (int G = 0; G < 2; ++G) {
                BSYNC(1 + G, 512);                 // wait z(G) ready
                const float* zb = zbuf + G * 288 + half * 36;
                u64 p[4];
#pragma unroll
                for (int r = 0; r < 4; ++r) {
                    const ulonglong2* zr =
                        reinterpret_cast<const ulonglong2*>(zb + r * ZZ);
                    u64 a0 = 0ull, a1 = 0ull, c0 = 0ull, c1 = 0ull;
#pragma unroll
                    for (int i = 0; i < 9; ++i) {  // 9 LDS.128, 36 FMA2
                        ulonglong2 zz = zr[i];
                        a0 = fma2(zz.x, w1a[2 * i],     a0);
                        a1 = fma2(zz.y, w1a[2 * i + 1], a1);
                        c0 = fma2(zz.x, w1b[2 * i],     c0);
                        c1 = fma2(zz.y, w1b[2 * i + 1], c1);
                    }
                    float2 fa = unpack2(a0), fb = unpack2(a1);
                    float2 fc = unpack2(c0), fd = unpack2(c1);
                    p[r] = pack2((fa.x + fa.y) + (fb.x + fb.y),
                                 (fc.x + fc.y) + (fd.x + fd.y));
                }
                // exchange: send p[dr+q], receive partner's p[fr+q]
#pragma unroll
                for (int q = 0; q < 2; ++q) {
                    u64 pp = __shfl_xor_sync(0xffffffffu, p[dr + q], 1);
                    float2 mine = unpack2(p[fr + q]), oth = unpack2(pp);
                    hq[G * 512 + (fr + q) * 128 + t] =
                        pack2(fast_tanh(mine.x + oth.x + b10),
                              fast_tanh(mine.y + oth.y + b11));
                }
                BARV(3 + G, 512);                  // h(G) ready
            }
        }
    } else {
        // ================= LAYER-2 WORKERS (warps 8-15) =================
        // thread (pg, dp): cols 2dp, 2dp+1; K-slice [pg*32, +32).
        // Owner of state element (er = pg&3, edc = 2dp + (pg>>2)) per group.
        const int i2 = tid - 256;
        const int pg = i2 >> 5;
        const int dp = i2 & 31;
        const int c0 = 2 * dp;
        const int er  = pg & 3;
        const int edc = c0 + (pg >> 2);
        u64 w2a[16], w2b[16];
#pragma unroll
        for (int i = 0; i < 16; ++i) {
            int k = pg * 32 + 2 * i;
            w2a[i] = pack2(W2g[k * DD + c0],     W2g[(k + 1) * DD + c0]);
            w2b[i] = pack2(W2g[k * DD + c0 + 1], W2g[(k + 1) * DD + c0 + 1]);
        }
        const float b2d = b2g[edc];
        float xc[2], kk[2][6];
#pragma unroll
        for (int G = 0; G < 2; ++G) {
            int grow = b0 + G * 4 + er;
            xc[G] = x0g[(size_t)grow * DD + edc];
            out[(size_t)grow * (TT * DD) + edc] = xc[G];   // t index 0
        }

        __syncthreads();               // init complete

        // prologue: z for stage 0 of substep 0, both groups
#pragma unroll
        for (int G = 0; G < 2; ++G) {
            zbuf[G * 288 + er * ZZ + edc] = xc[G];
            if (i2 < 32) u_interp(zbuf + G * 288, tu, ubuf, G, i2, te[0]);
            BARV(1 + G, 512);
        }

        for (int m = 0; m < 196; ++m) {
            const int ci = m >> 2, s = m & 3;
            const float tc0 = te[ci];
            const float dtc = te[ci + 1] - tc0;
            const float dt  = dtc * 0.25f;
            const float tsub = tc0 + dtc * ((float)s * 0.25f);
#pragma unroll
            for (int st = 0; st < 6; ++st) {
#pragma unroll
                for (int G = 0; G < 2; ++G) {
                    BSYNC(3 + G, 512);             // wait h(G)
                    const float* hb = hbuf + G * 1024 + pg * 32;
#pragma unroll
                    for (int r = 0; r < 4; ++r) {
                        const ulonglong2* hr =
                            reinterpret_cast<const ulonglong2*>(hb + r * HH);
                        u64 a0 = 0ull, a1 = 0ull, d0 = 0ull, d1 = 0ull;
#pragma unroll
                        for (int i = 0; i < 8; ++i) {  // 8 LDS.128, 32 FMA2
                            ulonglong2 hh = hr[i];
                            a0 = fma2(hh.x, w2a[2 * i],     a0);
                            a1 = fma2(hh.y, w2a[2 * i + 1], a1);
                            d0 = fma2(hh.x, w2b[2 * i],     d0);
                            d1 = fma2(hh.y, w2b[2 * i + 1], d1);
                        }
                        float2 fa = unpack2(a0), fb = unpack2(a1);
                        float2 fc = unpack2(d0), fd = unpack2(d1);
                        p2q[r * 256 + pg * 32 + dp] =
                            pack2((fa.x + fa.y) + (fb.x + fb.y),
                                  (fc.x + fc.y) + (fd.x + fd.y));
                    }
                    BSYNC(6, 256);                 // L2-internal
                    // owner: reduce 8 K-slices for my element
                    const float* pe = p2 + er * 512 + edc;
                    float kv = b2d;
#pragma unroll
                    for (int pgi = 0; pgi < 8; ++pgi) kv += pe[pgi * 64];
                    kk[G][st] = kv;

                    float* zG = zbuf + G * 288;
                    if (st < 5) {
                        float xs;
                        switch (st) {
                        case 0: xs = xc[G] + dt * (A21 * kk[G][0]); break;
                        case 1: xs = xc[G] + dt * (A31 * kk[G][0] + A32 * kk[G][1]); break;
                        case 2: xs = xc[G] + dt * (A41 * kk[G][0] + A42 * kk[G][1]
                                                 + A43 * kk[G][2]); break;
                        case 3: xs = xc[G] + dt * (A51 * kk[G][0] + A52 * kk[G][1]
                                                 + A53 * kk[G][2] + A54 * kk[G][3]); break;
                        default: xs = xc[G] + dt * (A61 * kk[G][0] + A62 * kk[G][1]
                                                  + A63 * kk[G][2] + A64 * kk[G][3]
                                                  + A65 * kk[G][4]); break;
                        }
                        zG[er * ZZ + edc] = xs;
                        if (i2 < 32) {
                            const float CSTN[5] = {0.2f, 0.3f, 0.8f,
                                                   (float)(8.0/9.0), 1.0f};
                            u_interp(zG, tu, ubuf, G, i2, tsub + CSTN[st] * dt);
                        }
                        BARV(1 + G, 512);          // z(G) ready
                    } else {
                        float xn = xc[G] + dt * (B1 * kk[G][0] + B3 * kk[G][2]
                                               + B4 * kk[G][3] + B5 * kk[G][4]
                                               + B6 * kv);
                        xc[G] = xn;
                        if (s == 3)
                            out[(size_t)(b0 + G * 4 + er) * (TT * DD)
                                + (ci + 1) * DD + edc] = xn;
                        if (m < 195) {
                            zG[er * ZZ + edc] = xn;
                            float tn = (s < 3)
                                ? tc0 + dtc * ((float)(s + 1) * 0.25f)
                                : te[ci + 1];
                            if (i2 < 32) u_interp(zG, tu, ubuf, G, i2, tn);
                            BARV(1 + G, 512);      // z(G) ready
                        }
                    }
                }
            }
        }
    }
}

extern "C" void kernel_launch(void* const* d_in, const int* in_sizes, int n_in,
                              void* d_out, int out_size) {
    const float* x0 = (const float*)d_in[0];
    const float* te = (const float*)d_in[1];
    const float* tu = (const float*)d_in[2];
    const float* ub = (const float*)d_in[3];
    const float* W1 = (const float*)d_in[4];
    const float* b1 = (const float*)d_in[5];
    const float* W2 = (const float*)d_in[6];
    const float* b2 = (const float*)d_in[7];
    float* out = (float*)d_out;

    const int smem_bytes = SMEM_FLOATS * (int)sizeof(float);   // 52224 B
    cudaFuncSetAttribute(node_kernel,
                         cudaFuncAttributeMaxDynamicSharedMemorySize, smem_bytes);
    node_kernel<<<CTAS, NT, smem_bytes>>>(x0, te, tu, ub, W1, b1, W2, b2, out);
}

// round 10
// speedup vs baseline: 1.3886x; 1.0190x over previous
#include <cuda_runtime.h>

#define DD 64
#define FF 8
#define ZZ 72          // D + F
#define HH 256
#define TT 50
#define TUU 128
#define CTAS 148
#define NT 512

typedef unsigned long long u64;

__device__ __forceinline__ u64 fma2(u64 a, u64 b, u64 c) {
    u64 d;
    asm("fma.rn.f32x2 %0, %1, %2, %3;" : "=l"(d) : "l"(a), "l"(b), "l"(c));
    return d;
}
__device__ __forceinline__ u64 pack2(float lo, float hi) {
    u64 d;
    asm("mov.b64 %0, {%1, %2};" : "=l"(d) : "f"(lo), "f"(hi));
    return d;
}
__device__ __forceinline__ float2 unpack2(u64 v) {
    float lo, hi;
    asm("mov.b64 {%0, %1}, %2;" : "=f"(lo), "=f"(hi) : "l"(v));
    return make_float2(lo, hi);
}
// tanh(x) = 1 - 2/(exp(2x)+1) via ex2.approx + rcp.approx, abs err ~1e-6.
__device__ __forceinline__ float fast_tanh(float x) {
    float e, r;
    asm("ex2.approx.f32 %0, %1;" : "=f"(e) : "f"(x * 2.8853900817779268f));
    asm("rcp.approx.f32 %0, %1;" : "=f"(r) : "f"(e + 1.0f));
    return fmaf(-2.0f, r, 1.0f);
}

// Named barriers (id 0 reserved for __syncthreads):
//   1+G : zready[G]  (L2 arrives 256, L1 syncs 256; count 512)
//   3+G : hready[G]  (L1 arrives 256, L2 syncs 256; count 512)
//   5   : L1-internal combine barrier (count 256)
//   6   : L2-internal partial barrier (count 256)
#define BSYNC(id, cnt) asm volatile("bar.sync %0, %1;"   :: "r"(id), "n"(cnt) : "memory")
#define BARV(id, cnt)  asm volatile("bar.arrive %0, %1;" :: "r"(id), "n"(cnt) : "memory")

// SMEM floats: ubuf 7*128*8=7168 | zbuf 2*288=576 | hbuf 2*1024=2048 |
//              p1 1024 ([4][128] u64) | p2 2048 | te 64 | tu 128
#define SMEM_FLOATS (7168 + 576 + 2048 + 1024 + 2048 + 64 + 128)

// exact jnp.searchsorted(side='right')-1 semantics
__device__ __forceinline__ void u_interp(float* zG, const float* tu,
                                         const float* ub, int gbase, int i2,
                                         float tst) {
    int r = i2 >> 3, f = i2 & 7;
    int idx = (int)floorf(tst * (float)(TUU - 1));
    idx = max(0, min(TUU - 2, idx));
    while (idx > 0 && tu[idx] > tst) --idx;
    while (idx < TUU - 2 && tu[idx + 1] <= tst) ++idx;
    float t0 = tu[idx], t1 = tu[idx + 1];
    float w = (tst - t0) / (t1 - t0);
    const float* ur = ub + (gbase + r) * (TUU * FF);
    float u0 = ur[idx * FF + f], u1 = ur[(idx + 1) * FF + f];
    zG[r * ZZ + DD + f] = u0 + w * (u1 - u0);
}

__global__ void __launch_bounds__(NT, 1)
node_kernel(const float* __restrict__ x0g, const float* __restrict__ te_g,
            const float* __restrict__ tu_g, const float* __restrict__ u_g,
            const float* __restrict__ W1g, const float* __restrict__ b1g,
            const float* __restrict__ W2g, const float* __restrict__ b2g,
            float* __restrict__ out)
{
    extern __shared__ float sm[];
    float* ubuf = sm;                  // [7][TUU][FF] (max NR=7)
    float* zbuf = ubuf + 7168;         // [2][4][ZZ]
    float* hbuf = zbuf + 576;          // [2][4][HH]
    float* p1   = hbuf + 2048;         // [4][128] u64 -> 1024 floats
    float* p2   = p1 + 1024;           // [4][8][64] layer-2 partials
    float* te   = p2 + 2048;           // [64]
    float* tu   = te + 64;             // [TUU]
    u64* hq  = reinterpret_cast<u64*>(hbuf);
    u64* p1q = reinterpret_cast<u64*>(p1);   // [row 0..3][t 0..127]
    u64* p2q = reinterpret_cast<u64*>(p2);

    const int tid = threadIdx.x;
    const int cta = blockIdx.x;
    // 136 CTAs x 7 rows + 12 CTAs x 6 rows = 1024
    const int NR  = (cta < 136) ? 7 : 6;
    const int b0  = (cta < 136) ? cta * 7 : 952 + (cta - 136) * 6;
    const int g0n = NR - 3;            // rows in group 0 (4 or 3); group 1 has 3

    // ---- one-time smem loads ----
    for (int i = tid; i < TT;  i += NT) te[i] = te_g[i];
    for (int i = tid; i < TUU; i += NT) tu[i] = tu_g[i];
    for (int i = tid; i < NR * TUU * FF; i += NT) {
        int r = i / (TUU * FF);
        int o = i - r * (TUU * FF);
        ubuf[i] = u_g[(size_t)(b0 + r) * (TUU * FF) + o];
    }

    // Dopri5 tableau (fp32-rounded)
    const float A21 = 0.2f;
    const float A31 = 0.075f,                    A32 = 0.225f;
    const float A41 = (float)( 44.0/45.0),       A42 = (float)(-56.0/15.0),
                A43 = (float)( 32.0/9.0);
    const float A51 = (float)( 19372.0/6561.0),  A52 = (float)(-25360.0/2187.0),
                A53 = (float)( 64448.0/6561.0),  A54 = (float)(-212.0/729.0);
    const float A61 = (float)( 9017.0/3168.0),   A62 = (float)(-355.0/33.0),
                A63 = (float)( 46732.0/5247.0),  A64 = (float)( 49.0/176.0),
                A65 = (float)(-5103.0/18656.0);
    const float B1  = (float)( 35.0/384.0),      B3  = (float)(500.0/1113.0),
                B4  = (float)(125.0/192.0),      B5  = (float)(-2187.0/6784.0),
                B6  = (float)( 11.0/84.0);

    if (tid < 256) {
        // ================= LAYER-1 WORKERS (warps 0-7) =================
        // thread (half, t): cols j0=2t, j0+1; K-half [half*36, +36)
        const int half = tid >> 7;
        const int t    = tid & 127;
        const int j0   = 2 * t;
        u64 w1a[18], w1b[18];
#pragma unroll
        for (int i = 0; i < 18; ++i) {
            int k = half * 36 + 2 * i;
            w1a[i] = pack2(W1g[k * HH + j0],     W1g[(k + 1) * HH + j0]);
            w1b[i] = pack2(W1g[k * HH + j0 + 1], W1g[(k + 1) * HH + j0 + 1]);
        }
        const float b10 = b1g[j0], b11 = b1g[j0 + 1];
        const int mr = half ? 2 : 0;   // rows I combine: {mr, mr+1}
        const int dr = 2 - mr;         // rows I donate

        __syncthreads();               // init complete

        for (int it = 0; it < 196 * 6; ++it) {
#pragma unroll
            for (int G = 0; G < 2; ++G) {
                const int nr = G ? 3 : g0n;
                BSYNC(1 + G, 512);                 // wait z(G) ready
                const float* zb = zbuf + G * 288 + half * 36;
                float pr0[4], pr1[4];
#pragma unroll
                for (int r = 0; r < 4; ++r) {
                    if (r < nr) {
                        const ulonglong2* zr =
                            reinterpret_cast<const ulonglong2*>(zb + r * ZZ);
                        u64 a0 = 0ull, a1 = 0ull, c0 = 0ull, c1 = 0ull;
#pragma unroll
                        for (int i = 0; i < 9; ++i) {  // 9 LDS.128, 36 FMA2
                            ulonglong2 zz = zr[i];
                            a0 = fma2(zz.x, w1a[2 * i],     a0);
                            a1 = fma2(zz.y, w1a[2 * i + 1], a1);
                            c0 = fma2(zz.x, w1b[2 * i],     c0);
                            c1 = fma2(zz.y, w1b[2 * i + 1], c1);
                        }
                        float2 fa = unpack2(a0), fb = unpack2(a1);
                        float2 fc = unpack2(c0), fd = unpack2(c1);
                        pr0[r] = (fa.x + fa.y) + (fb.x + fb.y);
                        pr1[r] = (fc.x + fc.y) + (fd.x + fd.y);
                    }
                }
                // donate partner's rows into absolute row slots (disjoint per half)
#pragma unroll
                for (int q = 0; q < 2; ++q)
                    if (dr + q < nr)
                        p1q[(dr + q) * 128 + t] = pack2(pr0[dr + q], pr1[dr + q]);
                BSYNC(5, 256);                     // L1-internal
                // combine my rows + tanh -> hbuf
#pragma unroll
                for (int q = 0; q < 2; ++q) {
                    int r = mr + q;
                    if (r < nr) {
                        float2 pp = unpack2(p1q[r * 128 + t]);
                        hq[G * 512 + r * 128 + t] =
                            pack2(fast_tanh(pr0[r] + pp.x + b10),
                                  fast_tanh(pr1[r] + pp.y + b11));
                    }
                }
                BARV(3 + G, 512);                  // h(G) ready
            }
        }
    } else {
        // ================= LAYER-2 WORKERS (warps 8-15) =================
        // thread (pg, dp): cols 2dp, 2dp+1; K-slice [pg*32, +32).
        // Owner of state element (er = pg&3, edc = 2dp + (pg>>2)) per group,
        // active only when er < nr(G).
        const int i2 = tid - 256;
        const int pg = i2 >> 5;
        const int dp = i2 & 31;
        const int c0 = 2 * dp;
        const int er  = pg & 3;
        const int edc = c0 + (pg >> 2);
        u64 w2a[16], w2b[16];
#pragma unroll
        for (int i = 0; i < 16; ++i) {
            int k = pg * 32 + 2 * i;
            w2a[i] = pack2(W2g[k * DD + c0],     W2g[(k + 1) * DD + c0]);
            w2b[i] = pack2(W2g[k * DD + c0 + 1], W2g[(k + 1) * DD + c0 + 1]);
        }
        const float b2d = b2g[edc];
        float xc[2], kk[2][6];
#pragma unroll
        for (int G = 0; G < 2; ++G) {
            const int nr = G ? 3 : g0n;
            if (er < nr) {
                int grow = b0 + (G ? g0n : 0) + er;
                xc[G] = x0g[(size_t)grow * DD + edc];
                out[(size_t)grow * (TT * DD) + edc] = xc[G];   // t index 0
            }
        }

        __syncthreads();               // init complete

        // prologue: z for stage 0 of substep 0, both groups
#pragma unroll
        for (int G = 0; G < 2; ++G) {
            const int nr = G ? 3 : g0n;
            if (er < nr) zbuf[G * 288 + er * ZZ + edc] = xc[G];
            if (i2 < nr * 8)
                u_interp(zbuf + G * 288, tu, ubuf, G ? g0n : 0, i2, te[0]);
            BARV(1 + G, 512);
        }

        for (int m = 0; m < 196; ++m) {
            const int ci = m >> 2, s = m & 3;
            const float tc0 = te[ci];
            const float dtc = te[ci + 1] - tc0;
            const float dt  = dtc * 0.25f;
            const float tsub = tc0 + dtc * ((float)s * 0.25f);
#pragma unroll
            for (int st = 0; st < 6; ++st) {
#pragma unroll
                for (int G = 0; G < 2; ++G) {
                    const int nr = G ? 3 : g0n;
                    BSYNC(3 + G, 512);             // wait h(G)
                    const float* hb = hbuf + G * 1024 + pg * 32;
#pragma unroll
                    for (int r = 0; r < 4; ++r) {
                        if (r < nr) {
                            const ulonglong2* hr =
                                reinterpret_cast<const ulonglong2*>(hb + r * HH);
                            u64 a0 = 0ull, a1 = 0ull, d0 = 0ull, d1 = 0ull;
#pragma unroll
                            for (int i = 0; i < 8; ++i) {  // 8 LDS.128, 32 FMA2
                                ulonglong2 hh = hr[i];
                                a0 = fma2(hh.x, w2a[2 * i],     a0);
                                a1 = fma2(hh.y, w2a[2 * i + 1], a1);
                                d0 = fma2(hh.x, w2b[2 * i],     d0);
                                d1 = fma2(hh.y, w2b[2 * i + 1], d1);
                            }
                            float2 fa = unpack2(a0), fb = unpack2(a1);
                            float2 fc = unpack2(d0), fd = unpack2(d1);
                            p2q[r * 256 + pg * 32 + dp] =
                                pack2((fa.x + fa.y) + (fb.x + fb.y),
                                      (fc.x + fc.y) + (fd.x + fd.y));
                        }
                    }
                    BSYNC(6, 256);                 // L2-internal
                    float* zG = zbuf + G * 288;
                    const bool own = (er < nr);
                    float kv = 0.0f;
                    if (own) {
                        const float* pe = p2 + er * 512 + edc;
                        kv = b2d;
#pragma unroll
                        for (int pgi = 0; pgi < 8; ++pgi) kv += pe[pgi * 64];
                        kk[G][st] = kv;
                    }
                    if (st < 5) {
                        if (own) {
                            float xs;
                            switch (st) {
                            case 0: xs = xc[G] + dt * (A21 * kk[G][0]); break;
                            case 1: xs = xc[G] + dt * (A31 * kk[G][0] + A32 * kk[G][1]); break;
                            case 2: xs = xc[G] + dt * (A41 * kk[G][0] + A42 * kk[G][1]
                                                     + A43 * kk[G][2]); break;
                            case 3: xs = xc[G] + dt * (A51 * kk[G][0] + A52 * kk[G][1]
                                                     + A53 * kk[G][2] + A54 * kk[G][3]); break;
                            default: xs = xc[G] + dt * (A61 * kk[G][0] + A62 * kk[G][1]
                                                      + A63 * kk[G][2] + A64 * kk[G][3]
                                                      + A65 * kk[G][4]); break;
                            }
                            zG[er * ZZ + edc] = xs;
                        }
                        if (i2 < nr * 8) {
                            const float CSTN[5] = {0.2f, 0.3f, 0.8f,
                                                   (float)(8.0/9.0), 1.0f};
                            u_interp(zG, tu, ubuf, G ? g0n : 0, i2,
                                     tsub + CSTN[st] * dt);
                        }
                        BARV(1 + G, 512);          // z(G) ready
                    } else {
                        const bool last = (m == 195);
                        if (own) {
                            float xn = xc[G] + dt * (B1 * kk[G][0] + B3 * kk[G][2]
                                                   + B4 * kk[G][3] + B5 * kk[G][4]
                                                   + B6 * kv);
                            xc[G] = xn;
                            if (s == 3)
                                out[(size_t)(b0 + (G ? g0n : 0) + er) * (TT * DD)
                                    + (ci + 1) * DD + edc] = xn;
                            if (!last) zG[er * ZZ + edc] = xn;
                        }
                        if (!last) {
                            float tn = (s < 3)
                                ? tc0 + dtc * ((float)(s + 1) * 0.25f)
                                : te[ci + 1];
                            if (i2 < nr * 8)
                                u_interp(zG, tu, ubuf, G ? g0n : 0, i2, tn);
                            BARV(1 + G, 512);      // z(G) ready
                        }
                    }
                }
            }
        }
    }
}

extern "C" void kernel_launch(void* const* d_in, const int* in_sizes, int n_in,
                              void* d_out, int out_size) {
    const float* x0 = (const float*)d_in[0];
    const float* te = (const float*)d_in[1];
    const float* tu = (const float*)d_in[2];
    const float* ub = (const float*)d_in[3];
    const float* W1 = (const float*)d_in[4];
    const float* b1 = (const float*)d_in[5];
    const float* W2 = (const float*)d_in[6];
    const float* b2 = (const float*)d_in[7];
    float* out = (float*)d_out;

    const int smem_bytes = SMEM_FLOATS * (int)sizeof(float);   // 52224 B
    cudaFuncSetAttribute(node_kernel,
                         cudaFuncAttributeMaxDynamicSharedMemorySize, smem_bytes);
    node_kernel<<<CTAS, NT, smem_bytes>>>(x0, te, tu, ub, W1, b1, W2, b2, out);
}

// round 11
// speedup vs baseline: 1.5213x; 1.0956x over previous
#include <cuda_runtime.h>

#define DD 64
#define FF 8
#define ZZ 72          // D + F
#define HH 256
#define TT 50
#define TUU 128
#define CTAS 148
#define NT 512

typedef unsigned long long u64;

__device__ __forceinline__ u64 fma2(u64 a, u64 b, u64 c) {
    u64 d;
    asm("fma.rn.f32x2 %0, %1, %2, %3;" : "=l"(d) : "l"(a), "l"(b), "l"(c));
    return d;
}
__device__ __forceinline__ u64 pack2(float lo, float hi) {
    u64 d;
    asm("mov.b64 %0, {%1, %2};" : "=l"(d) : "f"(lo), "f"(hi));
    return d;
}
__device__ __forceinline__ float2 unpack2(u64 v) {
    float lo, hi;
    asm("mov.b64 {%0, %1}, %2;" : "=f"(lo), "=f"(hi) : "l"(v));
    return make_float2(lo, hi);
}
// tanh(x) = 1 - 2/(exp(2x)+1) via ex2.approx + rcp.approx, abs err ~1e-6.
__device__ __forceinline__ float fast_tanh(float x) {
    float e, r;
    asm("ex2.approx.f32 %0, %1;" : "=f"(e) : "f"(x * 2.8853900817779268f));
    asm("rcp.approx.f32 %0, %1;" : "=f"(r) : "f"(e + 1.0f));
    return fmaf(-2.0f, r, 1.0f);
}

// Named barriers (id 0 reserved for __syncthreads):
//   1+G : zready[G]  (L2 arrives 256, L1 syncs 256; count 512)
//   3+G : hready[G]  (L1 arrives 256, L2 syncs 256; count 512)
//   5   : L1-internal combine barrier (count 256)
//   6   : L2-internal partial barrier (count 256)
#define BSYNC(id, cnt) asm volatile("bar.sync %0, %1;"   :: "r"(id), "n"(cnt) : "memory")
#define BARV(id, cnt)  asm volatile("bar.arrive %0, %1;" :: "r"(id), "n"(cnt) : "memory")

// SMEM floats: ubuf 7*128*8=7168 | zbuf 2*288=576 | hbuf 2*1024=2048 |
//              p1 1024 | p2 2048 | te 64 | tu 128
#define SMEM_FLOATS (7168 + 576 + 2048 + 1024 + 2048 + 64 + 128)

// exact jnp.searchsorted(side='right')-1 semantics
__device__ __forceinline__ void u_interp(float* zG, const float* tu,
                                         const float* ub, int gbase, int i2,
                                         float tst) {
    int r = i2 >> 3, f = i2 & 7;
    int idx = (int)floorf(tst * (float)(TUU - 1));
    idx = max(0, min(TUU - 2, idx));
    while (idx > 0 && tu[idx] > tst) --idx;
    while (idx < TUU - 2 && tu[idx + 1] <= tst) ++idx;
    float t0 = tu[idx], t1 = tu[idx + 1];
    float w = (tst - t0) / (t1 - t0);
    const float* ur = ub + (gbase + r) * (TUU * FF);
    float u0 = ur[idx * FF + f], u1 = ur[(idx + 1) * FF + f];
    zG[r * ZZ + DD + f] = u0 + w * (u1 - u0);
}

// ============ fully specialized worker body: G0N rows in group0, 3 in group1 ============
template <int G0N>
__device__ __forceinline__ void run_cta(
    float* sm, int tid, int b0,
    const float* __restrict__ x0g, const float* __restrict__ W1g,
    const float* __restrict__ b1g, const float* __restrict__ W2g,
    const float* __restrict__ b2g, float* __restrict__ out)
{
    constexpr int NRR = G0N + 3;
    float* ubuf = sm;                  // [NRR][TUU][FF]
    float* zbuf = ubuf + 7168;         // [2][4][ZZ]
    float* hbuf = zbuf + 576;          // [2][4][HH]
    float* p1   = hbuf + 2048;         // [4][128] u64 -> 1024 floats
    float* p2   = p1 + 1024;           // [4][8][64]
    float* te   = p2 + 2048;           // [64]
    float* tu   = te + 64;             // [TUU]
    u64* hq  = reinterpret_cast<u64*>(hbuf);
    u64* p1q = reinterpret_cast<u64*>(p1);
    u64* p2q = reinterpret_cast<u64*>(p2);

    // Dopri5 tableau (fp32-rounded)
    const float A21 = 0.2f;
    const float A31 = 0.075f,                    A32 = 0.225f;
    const float A41 = (float)( 44.0/45.0),       A42 = (float)(-56.0/15.0),
                A43 = (float)( 32.0/9.0);
    const float A51 = (float)( 19372.0/6561.0),  A52 = (float)(-25360.0/2187.0),
                A53 = (float)( 64448.0/6561.0),  A54 = (float)(-212.0/729.0);
    const float A61 = (float)( 9017.0/3168.0),   A62 = (float)(-355.0/33.0),
                A63 = (float)( 46732.0/5247.0),  A64 = (float)( 49.0/176.0),
                A65 = (float)(-5103.0/18656.0);
    const float B1  = (float)( 35.0/384.0),      B3  = (float)(500.0/1113.0),
                B4  = (float)(125.0/192.0),      B5  = (float)(-2187.0/6784.0),
                B6  = (float)( 11.0/84.0);

    if (tid < 256) {
        // ---------------- LAYER-1 WORKERS (warps 0-7) ----------------
        const int half = tid >> 7;
        const int t    = tid & 127;
        const int j0   = 2 * t;
        u64 w1a[18], w1b[18];
#pragma unroll
        for (int i = 0; i < 18; ++i) {
            int k = half * 36 + 2 * i;
            w1a[i] = pack2(W1g[k * HH + j0],     W1g[(k + 1) * HH + j0]);
            w1b[i] = pack2(W1g[k * HH + j0 + 1], W1g[(k + 1) * HH + j0 + 1]);
        }
        const float b10 = b1g[j0], b11 = b1g[j0 + 1];
        const int mr = half ? 2 : 0;   // rows I combine
        const int dr = 2 - mr;         // rows I donate

        __syncthreads();               // init complete

        for (int it = 0; it < 196 * 6; ++it) {
#pragma unroll
            for (int G = 0; G < 2; ++G) {
                constexpr int NRG0 = G0N;   // for clarity
                const int nr = (G == 0) ? NRG0 : 3;   // constexpr after unroll
                BSYNC(1 + G, 512);                 // wait z(G) ready
                const float* zb = zbuf + G * 288 + half * 36;
                float pr0[4], pr1[4];
#pragma unroll
                for (int r = 0; r < 4; ++r) {
                    if (r < nr) {
                        const ulonglong2* zr =
                            reinterpret_cast<const ulonglong2*>(zb + r * ZZ);
                        u64 a0 = 0ull, a1 = 0ull, c0 = 0ull, c1 = 0ull;
#pragma unroll
                        for (int i = 0; i < 9; ++i) {  // 9 LDS.128, 36 FMA2
                            ulonglong2 zz = zr[i];
                            a0 = fma2(zz.x, w1a[2 * i],     a0);
                            a1 = fma2(zz.y, w1a[2 * i + 1], a1);
                            c0 = fma2(zz.x, w1b[2 * i],     c0);
                            c1 = fma2(zz.y, w1b[2 * i + 1], c1);
                        }
                        float2 fa = unpack2(a0), fb = unpack2(a1);
                        float2 fc = unpack2(c0), fd = unpack2(c1);
                        pr0[r] = (fa.x + fa.y) + (fb.x + fb.y);
                        pr1[r] = (fc.x + fc.y) + (fd.x + fd.y);
                    }
                }
#pragma unroll
                for (int q = 0; q < 2; ++q)
                    if (dr + q < nr)   // dr runtime (half), nr constexpr
                        p1q[(dr + q) * 128 + t] = pack2(pr0[dr + q], pr1[dr + q]);
                BSYNC(5, 256);                     // L1-internal
#pragma unroll
                for (int q = 0; q < 2; ++q) {
                    int r = mr + q;
                    if (r < nr) {
                        float2 pp = unpack2(p1q[r * 128 + t]);
                        hq[G * 512 + r * 128 + t] =
                            pack2(fast_tanh(pr0[r] + pp.x + b10),
                                  fast_tanh(pr1[r] + pp.y + b11));
                    }
                }
                BARV(3 + G, 512);                  // h(G) ready
            }
        }
    } else {
        // ---------------- LAYER-2 WORKERS (warps 8-15) ----------------
        const int i2 = tid - 256;
        const int pg = i2 >> 5;
        const int dp = i2 & 31;
        const int c0 = 2 * dp;
        const int er  = pg & 3;
        const int edc = c0 + (pg >> 2);
        u64 w2a[16], w2b[16];
#pragma unroll
        for (int i = 0; i < 16; ++i) {
            int k = pg * 32 + 2 * i;
            w2a[i] = pack2(W2g[k * DD + c0],     W2g[(k + 1) * DD + c0]);
            w2b[i] = pack2(W2g[k * DD + c0 + 1], W2g[(k + 1) * DD + c0 + 1]);
        }
        const float b2d = b2g[edc];
        float xc[2], kk[2][6];
#pragma unroll
        for (int G = 0; G < 2; ++G) {
            const int nr = (G == 0) ? G0N : 3;
            if (er < nr) {
                int grow = b0 + (G ? G0N : 0) + er;
                xc[G] = x0g[(size_t)grow * DD + edc];
                out[(size_t)grow * (TT * DD) + edc] = xc[G];   // t index 0
            }
        }

        __syncthreads();               // init complete

        // prologue: z for stage 0 of substep 0, both groups
#pragma unroll
        for (int G = 0; G < 2; ++G) {
            const int nr = (G == 0) ? G0N : 3;
            if (er < nr) zbuf[G * 288 + er * ZZ + edc] = xc[G];
            if (i2 < nr * 8)
                u_interp(zbuf + G * 288, tu, ubuf, G ? G0N : 0, i2, te[0]);
            BARV(1 + G, 512);
        }

        for (int m = 0; m < 196; ++m) {
            const int ci = m >> 2, s = m & 3;
            const float tc0 = te[ci];
            const float dtc = te[ci + 1] - tc0;
            const float dt  = dtc * 0.25f;
            const float tsub = tc0 + dtc * ((float)s * 0.25f);
#pragma unroll
            for (int st = 0; st < 6; ++st) {
#pragma unroll
                for (int G = 0; G < 2; ++G) {
                    const int nr = (G == 0) ? G0N : 3;
                    BSYNC(3 + G, 512);             // wait h(G)
                    const float* hb = hbuf + G * 1024 + pg * 32;
#pragma unroll
                    for (int r = 0; r < 4; ++r) {
                        if (r < nr) {
                            const ulonglong2* hr =
                                reinterpret_cast<const ulonglong2*>(hb + r * HH);
                            u64 a0 = 0ull, a1 = 0ull, d0 = 0ull, d1 = 0ull;
#pragma unroll
                            for (int i = 0; i < 8; ++i) {  // 8 LDS.128, 32 FMA2
                                ulonglong2 hh = hr[i];
                                a0 = fma2(hh.x, w2a[2 * i],     a0);
                                a1 = fma2(hh.y, w2a[2 * i + 1], a1);
                                d0 = fma2(hh.x, w2b[2 * i],     d0);
                                d1 = fma2(hh.y, w2b[2 * i + 1], d1);
                            }
                            float2 fa = unpack2(a0), fb = unpack2(a1);
                            float2 fc = unpack2(d0), fd = unpack2(d1);
                            p2q[r * 256 + pg * 32 + dp] =
                                pack2((fa.x + fa.y) + (fb.x + fb.y),
                                      (fc.x + fc.y) + (fd.x + fd.y));
                        }
                    }
                    BSYNC(6, 256);                 // L2-internal
                    float* zG = zbuf + G * 288;
                    const bool own = (er < nr);    // constexpr-true when nr==4
                    float kv = 0.0f;
                    if (own) {
                        const float* pe = p2 + er * 512 + edc;
                        kv = b2d;
#pragma unroll
                        for (int pgi = 0; pgi < 8; ++pgi) kv += pe[pgi * 64];
                        kk[G][st] = kv;
                    }
                    if (st < 5) {
                        if (own) {
                            float xs;
                            switch (st) {
                            case 0: xs = xc[G] + dt * (A21 * kk[G][0]); break;
                            case 1: xs = xc[G] + dt * (A31 * kk[G][0] + A32 * kk[G][1]); break;
                            case 2: xs = xc[G] + dt * (A41 * kk[G][0] + A42 * kk[G][1]
                                                     + A43 * kk[G][2]); break;
                            case 3: xs = xc[G] + dt * (A51 * kk[G][0] + A52 * kk[G][1]
                                                     + A53 * kk[G][2] + A54 * kk[G][3]); break;
                            default: xs = xc[G] + dt * (A61 * kk[G][0] + A62 * kk[G][1]
                                                      + A63 * kk[G][2] + A64 * kk[G][3]
                                                      + A65 * kk[G][4]); break;
                            }
                            zG[er * ZZ + edc] = xs;
                        }
                        if (i2 < nr * 8) {
                            const float CSTN[5] = {0.2f, 0.3f, 0.8f,
                                                   (float)(8.0/9.0), 1.0f};
                            u_interp(zG, tu, ubuf, G ? G0N : 0, i2,
                                     tsub + CSTN[st] * dt);
                        }
                        BARV(1 + G, 512);          // z(G) ready
                    } else {
                        const bool last = (m == 195);
                        if (own) {
                            float xn = xc[G] + dt * (B1 * kk[G][0] + B3 * kk[G][2]
                                                   + B4 * kk[G][3] + B5 * kk[G][4]
                                                   + B6 * kv);
                            xc[G] = xn;
                            if (s == 3)
                                out[(size_t)(b0 + (G ? G0N : 0) + er) * (TT * DD)
                                    + (ci + 1) * DD + edc] = xn;
                            if (!last) zG[er * ZZ + edc] = xn;
                        }
                        if (!last) {
                            float tn = (s < 3)
                                ? tc0 + dtc * ((float)(s + 1) * 0.25f)
                                : te[ci + 1];
                            if (i2 < nr * 8)
                                u_interp(zG, tu, ubuf, G ? G0N : 0, i2, tn);
                            BARV(1 + G, 512);      // z(G) ready
                        }
                    }
                }
            }
        }
    }
}

__global__ void __launch_bounds__(NT, 1)
node_kernel(const float* __restrict__ x0g, const float* __restrict__ te_g,
            const float* __restrict__ tu_g, const float* __restrict__ u_g,
            const float* __restrict__ W1g, const float* __restrict__ b1g,
            const float* __restrict__ W2g, const float* __restrict__ b2g,
            float* __restrict__ out)
{
    extern __shared__ float sm[];
    const int tid = threadIdx.x;
    const int cta = blockIdx.x;
    // 136 CTAs x 7 rows + 12 CTAs x 6 rows = 1024
    const int NR  = (cta < 136) ? 7 : 6;
    const int b0  = (cta < 136) ? cta * 7 : 952 + (cta - 136) * 6;

    // one-time smem loads (common)
    float* te = sm + 7168 + 576 + 2048 + 1024 + 2048;
    float* tu = te + 64;
    for (int i = tid; i < TT;  i += NT) te[i] = te_g[i];
    for (int i = tid; i < TUU; i += NT) tu[i] = tu_g[i];
    for (int i = tid; i < NR * TUU * FF; i += NT) {
        int r = i / (TUU * FF);
        int o = i - r * (TUU * FF);
        sm[i] = u_g[(size_t)(b0 + r) * (TUU * FF) + o];
    }

    if (cta < 136)
        run_cta<4>(sm, tid, b0, x0g, W1g, b1g, W2g, b2g, out);
    else
        run_cta<3>(sm, tid, b0, x0g, W1g, b1g, W2g, b2g, out);
}

extern "C" void kernel_launch(void* const* d_in, const int* in_sizes, int n_in,
                              void* d_out, int out_size) {
    const float* x0 = (const float*)d_in[0];
    const float* te = (const float*)d_in[1];
    const float* tu = (const float*)d_in[2];
    const float* ub = (const float*)d_in[3];
    const float* W1 = (const float*)d_in[4];
    const float* b1 = (const float*)d_in[5];
    const float* W2 = (const float*)d_in[6];
    const float* b2 = (const float*)d_in[7];
    float* out = (float*)d_out;

    const int smem_bytes = SMEM_FLOATS * (int)sizeof(float);   // 52224 B
    cudaFuncSetAttribute(node_kernel,
                         cudaFuncAttributeMaxDynamicSharedMemorySize, smem_bytes);
    node_kernel<<<CTAS, NT, smem_bytes>>>(x0, te, tu, ub, W1, b1, W2, b2, out);
}